// round 4
// baseline (speedup 1.0000x reference)
#include <cuda_runtime.h>
#include <cstdint>

#define T_DIM 256
#define B_DIM 128
#define N_DIM 4
#define D_DIM 2
#define L_WIN 64

// ---------- f32x2 packed helpers (sm_100+) ----------
__device__ __forceinline__ unsigned long long pack2(float lo, float hi) {
    unsigned long long r;
    asm("mov.b64 %0, {%1, %2};" : "=l"(r) : "f"(lo), "f"(hi));
    return r;
}
__device__ __forceinline__ void unpack2(unsigned long long v, float& lo, float& hi) {
    asm("mov.b64 {%0, %1}, %2;" : "=f"(lo), "=f"(hi) : "l"(v));
}
__device__ __forceinline__ unsigned long long fma2(unsigned long long a,
                                                   unsigned long long b,
                                                   unsigned long long c) {
    unsigned long long d;
    asm("fma.rn.f32x2 %0, %1, %2, %3;" : "=l"(d) : "l"(a), "l"(b), "l"(c));
    return d;
}

// ---------- fast activations (MUFU EX2 + RCP, ~2 ulp) ----------
__device__ __forceinline__ float sigf(float x) {
    float e = __expf(-x);
    return __fdividef(1.0f, 1.0f + e);
}
__device__ __forceinline__ float tanh_fast(float x) {
    float e = __expf(2.0f * x);
    return 1.0f - __fdividef(2.0f, e + 1.0f);
}

// One warp per (t, b) sequence.
// Lane u owns hidden unit u of the H=32 "his" LSTM (h, c scalars).
// For the H=8 "int" LSTM, lane l computes gate row l (of 32 rows); units live in lanes 0..7.
__global__ void __launch_bounds__(128, 1) traj_kernel(
    const float* __restrict__ inputs,
    const float* __restrict__ Wih_his, const float* __restrict__ Whh_his,
    const float* __restrict__ bih_his, const float* __restrict__ bhh_his,
    const float* __restrict__ Wih_int, const float* __restrict__ Whh_int,
    const float* __restrict__ bih_int, const float* __restrict__ bhh_int,
    const float* __restrict__ W_out, const float* __restrict__ b_out,
    float* __restrict__ out)
{
    const unsigned FULL = 0xffffffffu;
    const int lane = threadIdx.x & 31;
    const int gw = blockIdx.x * (blockDim.x >> 5) + (threadIdx.x >> 5); // 0..32767
    const int t = (T_DIM - 1) - (gw >> 7);   // long windows scheduled first
    const int b = gw & (B_DIM - 1);

    // ---- load per-lane weight slices into registers ----
    // Whh_his: [128, 32] row-major; gate-g row for unit u is 32*g + u.
    unsigned long long w_if[32], w_go[32];
#pragma unroll
    for (int k = 0; k < 32; k++) {
        w_if[k] = pack2(Whh_his[(lane)      * 32 + k], Whh_his[(32 + lane) * 32 + k]);
        w_go[k] = pack2(Whh_his[(64 + lane) * 32 + k], Whh_his[(96 + lane) * 32 + k]);
    }
    // Wih_his: [128, 2]
    unsigned long long wx0_if = pack2(Wih_his[(lane) * 2 + 0],      Wih_his[(32 + lane) * 2 + 0]);
    unsigned long long wx1_if = pack2(Wih_his[(lane) * 2 + 1],      Wih_his[(32 + lane) * 2 + 1]);
    unsigned long long wx0_go = pack2(Wih_his[(64 + lane) * 2 + 0], Wih_his[(96 + lane) * 2 + 0]);
    unsigned long long wx1_go = pack2(Wih_his[(64 + lane) * 2 + 1], Wih_his[(96 + lane) * 2 + 1]);
    unsigned long long bb_if = pack2(bih_his[lane] + bhh_his[lane],
                                     bih_his[32 + lane] + bhh_his[32 + lane]);
    unsigned long long bb_go = pack2(bih_his[64 + lane] + bhh_his[64 + lane],
                                     bih_his[96 + lane] + bhh_his[96 + lane]);

    // int LSTM: lane computes gate row `lane` (32 rows x 8 cols)
    float wi_int[8];
#pragma unroll
    for (int k = 0; k < 8; k++) wi_int[k] = Whh_int[lane * 8 + k];
    const float wx0_int = Wih_int[lane * 2 + 0];
    const float wx1_int = Wih_int[lane * 2 + 1];
    const float b_int = bih_int[lane] + bhh_int[lane];
    // rows 16..23 are the g-gate -> tanh(x) = 2*sigmoid(2x) - 1
    const bool is_g = (lane >= 16) && (lane < 24);
    const float pre = is_g ? 2.0f : 1.0f;
    const float scl = is_g ? 2.0f : 1.0f;
    const float off = is_g ? -1.0f : 0.0f;

    // output head weights: W_out [2, 40]; emb = [h_his(32), h_int(8)]
    const float wo0  = W_out[lane];
    const float wo1  = W_out[40 + lane];
    const float wo0i = (lane < 8) ? W_out[32 + lane] : 0.0f;
    const float wo1i = (lane < 8) ? W_out[72 + lane] : 0.0f;

    // ---- recurrence over valid steps only ----
    int a0 = t - (L_WIN - 1);
    if (a0 < 0) a0 = 0;

    float h = 0.0f, c = 0.0f;   // his unit `lane`
    float hi = 0.0f, ci = 0.0f; // int unit (lane & 7), authoritative in lanes 0..7

    const float2* __restrict__ inp2 = (const float2*)inputs; // [T,B,N] of float2 (D=2)
    long base = ((long)a0 * B_DIM + b) * N_DIM;
    float2 xh = inp2[base + 3]; // node -1 -> index 3
    float2 xi = inp2[base + 0]; // node 0

    for (int a = a0; a <= t; a++) {
        // software prefetch next step's x
        float2 xh_n = xh, xi_n = xi;
        if (a < t) {
            long nb = ((long)(a + 1) * B_DIM + b) * N_DIM;
            xh_n = inp2[nb + 3];
            xi_n = inp2[nb + 0];
        }

        // --- his gates: packed (i,f) and (g,o) ---
        unsigned long long x0 = pack2(xh.x, xh.x);
        unsigned long long x1 = pack2(xh.y, xh.y);
        unsigned long long aif = fma2(x0, wx0_if, bb_if);
        unsigned long long ago = fma2(x0, wx0_go, bb_go);
        aif = fma2(x1, wx1_if, aif);
        ago = fma2(x1, wx1_go, ago);
#pragma unroll
        for (int k = 0; k < 32; k++) {
            float hk = __shfl_sync(FULL, h, k);
            unsigned long long hk2 = pack2(hk, hk);
            aif = fma2(hk2, w_if[k], aif);
            ago = fma2(hk2, w_go[k], ago);
        }

        // --- int gate row (scalar per lane) ---
        float gint = fmaf(xi.x, wx0_int, fmaf(xi.y, wx1_int, b_int));
#pragma unroll
        for (int k = 0; k < 8; k++) {
            float hik = __shfl_sync(FULL, hi, k);
            gint = fmaf(hik, wi_int[k], gint);
        }

        // --- his activations & state update ---
        float gi, gf, gg, go;
        unpack2(aif, gi, gf);
        unpack2(ago, gg, go);
        float si = sigf(gi), sf = sigf(gf), tg = tanh_fast(gg), so = sigf(go);
        c = fmaf(sf, c, si * tg);
        h = so * tanh_fast(c);

        // --- int activations: one sigmoid per gate row, then gather per unit ---
        float actv = fmaf(scl, sigf(pre * gint), off);
        int u8 = lane & 7;
        float ii = __shfl_sync(FULL, actv, u8);
        float ff = __shfl_sync(FULL, actv, u8 + 8);
        float g2 = __shfl_sync(FULL, actv, u8 + 16);
        float oo = __shfl_sync(FULL, actv, u8 + 24);
        ci = fmaf(ff, ci, ii * g2);
        hi = oo * tanh_fast(ci);

        xh = xh_n;
        xi = xi_n;
    }

    // ---- output head: warp reduction over the 40-dim embedding ----
    float s0 = fmaf(h, wo0, hi * wo0i);
    float s1 = fmaf(h, wo1, hi * wo1i);
#pragma unroll
    for (int d = 16; d > 0; d >>= 1) {
        s0 += __shfl_xor_sync(FULL, s0, d);
        s1 += __shfl_xor_sync(FULL, s1, d);
    }
    if (lane == 0) {
        float2 o;
        o.x = s0 + b_out[0];
        o.y = s1 + b_out[1];
        ((float2*)out)[t * B_DIM + b] = o;
    }
}

extern "C" void kernel_launch(void* const* d_in, const int* in_sizes, int n_in,
                              void* d_out, int out_size) {
    (void)in_sizes; (void)n_in; (void)out_size;
    const float* inputs  = (const float*)d_in[0];
    const float* Wih_his = (const float*)d_in[1];
    const float* Whh_his = (const float*)d_in[2];
    const float* bih_his = (const float*)d_in[3];
    const float* bhh_his = (const float*)d_in[4];
    const float* Wih_int = (const float*)d_in[5];
    const float* Whh_int = (const float*)d_in[6];
    const float* bih_int = (const float*)d_in[7];
    const float* bhh_int = (const float*)d_in[8];
    const float* W_out   = (const float*)d_in[9];
    const float* b_out   = (const float*)d_in[10];
    float* out = (float*)d_out;

    // 32768 sequences, one warp each: 8192 blocks x 128 threads (4 warps)
    traj_kernel<<<8192, 128>>>(inputs, Wih_his, Whh_his, bih_his, bhh_his,
                               Wih_int, Whh_int, bih_int, bhh_int,
                               W_out, b_out, out);
}